// round 2
// baseline (speedup 1.0000x reference)
#include <cuda_runtime.h>
#include <math.h>

#define T_TOK   16384
#define DIM     2048
#define N_EXP   64
#define NC      128        // combined columns: 64 gate + 64 noise
#define TM      64         // tokens per block
#define BK      16         // k-tile
#define TOPK    8

// scratch: combined logits [T_TOK][NC]  (8 MB, static device array — allowed)
__device__ float g_logits[(size_t)T_TOK * NC];

typedef unsigned long long ull;

__device__ __forceinline__ ull pack2(float lo, float hi) {
    ull r;
    asm("mov.b64 %0, {%1, %2};" : "=l"(r) : "f"(lo), "f"(hi));
    return r;
}
__device__ __forceinline__ void unpack2(ull v, float& lo, float& hi) {
    asm("mov.b64 {%0, %1}, %2;" : "=f"(lo), "=f"(hi) : "l"(v));
}
__device__ __forceinline__ void fma2(ull& d, ull a, ull b) {
    asm("fma.rn.f32x2 %0, %1, %2, %3;" : "=l"(d) : "l"(a), "l"(b), "l"(d));
}

// ---------------------------------------------------------------------------
// Kernel 1: C[t][0:64] = H[t]·Wg^T, C[t][64:128] = H[t]·Wn^T
// fp32 FFMA2 inner product, chunk-of-128 promotion into double accumulators
// (error ~1.4e-7 absolute vs ~1.6e-6 for straight sequential fp32).
// ---------------------------------------------------------------------------
__global__ void __launch_bounds__(256, 1)
router_gemm_kernel(const float* __restrict__ H,
                   const float* __restrict__ Wg,
                   const float* __restrict__ Wn) {
    __shared__ float As[BK][TM];   // 4 KB
    __shared__ float Bs[BK][NC];   // 8 KB

    const int tid = threadIdx.x;
    const int tx  = tid & 15;      // col group: cols {2tx+32i, +1}, i<4
    const int ty  = tid >> 4;      // row group: rows 4ty..4ty+3
    const int m0  = blockIdx.x * TM;

    // loaders
    const int a_row = tid & 63,  a_k4 = tid >> 6;   // A: 1 float4 / thread / tile
    const int b_row = tid & 127, b_k8 = tid >> 7;   // B: 2 float4 / thread / tile

    const float4* hrow = (const float4*)(H + (size_t)(m0 + a_row) * DIM);
    const float*  wp   = (b_row < N_EXP) ? (Wg + (size_t)b_row * DIM)
                                         : (Wn + (size_t)(b_row - N_EXP) * DIM);
    const float4* wrow = (const float4*)wp;

    ull    acc[4][4];     // fp32x2 chunk accumulators [row j][col-pair i]
    double dacc[4][8];    // exact chunk sums           [row j][col]
#pragma unroll
    for (int j = 0; j < 4; j++) {
#pragma unroll
        for (int i = 0; i < 4; i++) acc[j][i] = 0ULL;
#pragma unroll
        for (int c = 0; c < 8; c++) dacc[j][c] = 0.0;
    }

    // prefetch tile 0
    float4 av  = hrow[a_k4];
    float4 bv0 = wrow[2 * b_k8];
    float4 bv1 = wrow[2 * b_k8 + 1];

    for (int tile = 0; tile < DIM / BK; tile++) {
        __syncthreads();   // previous tile fully consumed
        {
            const int ka = a_k4 * 4;
            As[ka+0][a_row] = av.x; As[ka+1][a_row] = av.y;
            As[ka+2][a_row] = av.z; As[ka+3][a_row] = av.w;
            const int kb = b_k8 * 8;
            Bs[kb+0][b_row] = bv0.x; Bs[kb+1][b_row] = bv0.y;
            Bs[kb+2][b_row] = bv0.z; Bs[kb+3][b_row] = bv0.w;
            Bs[kb+4][b_row] = bv1.x; Bs[kb+5][b_row] = bv1.y;
            Bs[kb+6][b_row] = bv1.z; Bs[kb+7][b_row] = bv1.w;
        }
        __syncthreads();

        // prefetch next tile while FMAs run (hides DRAM latency at occ=1)
        if (tile + 1 < DIM / BK) {
            const int f4 = ((tile + 1) * BK) >> 2;
            av  = hrow[f4 + a_k4];
            bv0 = wrow[f4 + 2 * b_k8];
            bv1 = wrow[f4 + 2 * b_k8 + 1];
        }

#pragma unroll
        for (int k = 0; k < BK; k++) {
            float4 a4 = *(const float4*)&As[k][ty * 4];   // 4 rows, one LDS.128
            ull a2[4] = { pack2(a4.x, a4.x), pack2(a4.y, a4.y),
                          pack2(a4.z, a4.z), pack2(a4.w, a4.w) };
            ull b2[4];
#pragma unroll
            for (int i = 0; i < 4; i++)
                b2[i] = *(const ull*)&Bs[k][2 * tx + 32 * i];   // LDS.64
#pragma unroll
            for (int j = 0; j < 4; j++)
#pragma unroll
                for (int i = 0; i < 4; i++)
                    fma2(acc[j][i], a2[j], b2[i]);
        }

        // promote chunk (128 k-values) into double accumulators
        if ((tile & 7) == 7) {
#pragma unroll
            for (int j = 0; j < 4; j++)
#pragma unroll
                for (int i = 0; i < 4; i++) {
                    float lo, hi;
                    unpack2(acc[j][i], lo, hi);
                    dacc[j][2*i]   += (double)lo;
                    dacc[j][2*i+1] += (double)hi;
                    acc[j][i] = 0ULL;
                }
        }
    }

    // write logits tile
#pragma unroll
    for (int j = 0; j < 4; j++) {
        const int m = m0 + ty * 4 + j;
        float* dst = g_logits + (size_t)m * NC;
#pragma unroll
        for (int i = 0; i < 4; i++) {
            const int c = 2 * tx + 32 * i;
            dst[c]     = (float)dacc[j][2*i];
            dst[c + 1] = (float)dacc[j][2*i+1];
        }
    }
}

// ---------------------------------------------------------------------------
// Kernel 2: one warp per token — noisy logits, softmax(64), top-8 desc
// out layout (all fp32): [vals T*8][inds T*8 (cast)][gates T*64]
// ---------------------------------------------------------------------------
__device__ __forceinline__ float softplus_f(float x) {
    return fmaxf(x, 0.0f) + log1pf(expf(-fabsf(x)));
}

__global__ void __launch_bounds__(256)
router_topk_kernel(const float* __restrict__ noise, float* __restrict__ out) {
    const int warp = (blockIdx.x * blockDim.x + threadIdx.x) >> 5;
    const int lane = threadIdx.x & 31;
    if (warp >= T_TOK) return;

    const float* row = g_logits + (size_t)warp * NC;
    const float* nz  = noise + (size_t)warp * N_EXP;

    // expert e = lane and e = lane+32
    float g0 = row[lane]      + nz[lane]      * softplus_f(row[64 + lane]);
    float g1 = row[lane + 32] + nz[lane + 32] * softplus_f(row[96 + lane]);

    // softmax over 64
    float mx = fmaxf(g0, g1);
#pragma unroll
    for (int o = 16; o > 0; o >>= 1) mx = fmaxf(mx, __shfl_xor_sync(0xffffffffu, mx, o));
    float e0 = expf(g0 - mx), e1 = expf(g1 - mx);
    float s = e0 + e1;
#pragma unroll
    for (int o = 16; o > 0; o >>= 1) s += __shfl_xor_sync(0xffffffffu, s, o);
    const float inv = 1.0f / s;
    float p0 = e0 * inv, p1 = e1 * inv;

    // write gates
    float* gates = out + (size_t)2 * T_TOK * TOPK + (size_t)warp * N_EXP;
    gates[lane]      = p0;
    gates[lane + 32] = p1;

    // top-8, sorted desc, lower index on ties (matches jax.lax.top_k)
    float v0 = p0, v1 = p1;
    float* vals = out + (size_t)warp * TOPK;
    float* inds = out + (size_t)T_TOK * TOPK + (size_t)warp * TOPK;

#pragma unroll
    for (int r = 0; r < TOPK; r++) {
        float cv; int ci;
        if (v0 >= v1) { cv = v0; ci = lane; }       // lower index wins ties
        else          { cv = v1; ci = lane + 32; }
#pragma unroll
        for (int o = 16; o > 0; o >>= 1) {
            float ov = __shfl_xor_sync(0xffffffffu, cv, o);
            int   oi = __shfl_xor_sync(0xffffffffu, ci, o);
            if (ov > cv || (ov == cv && oi < ci)) { cv = ov; ci = oi; }
        }
        if (lane == 0) {
            vals[r] = cv;
            inds[r] = (float)ci;
        }
        // remove selected
        if (ci == lane)      v0 = -INFINITY;
        if (ci == lane + 32) v1 = -INFINITY;
    }
}

// ---------------------------------------------------------------------------
extern "C" void kernel_launch(void* const* d_in, const int* in_sizes, int n_in,
                              void* d_out, int out_size) {
    const float* H     = (const float*)d_in[0];  // [4,4096,2048]
    const float* Wg    = (const float*)d_in[1];  // [64,2048]
    const float* Wn    = (const float*)d_in[2];  // [64,2048]
    const float* noise = (const float*)d_in[3];  // [4,4096,64]
    float* out = (float*)d_out;

    router_gemm_kernel<<<T_TOK / TM, 256>>>(H, Wg, Wn);
    router_topk_kernel<<<(T_TOK * 32) / 256, 256>>>(noise, out);
}